// round 8
// baseline (speedup 1.0000x reference)
#include <cuda_runtime.h>
#include <math.h>
#include <stdint.h>

#define TOK   1024   // B*S
#define SLEN  256
#define BATCH 4
#define HID   512
#define DINP  1024
#define GHID  2048
#define NPRE  4096   // 2 dirs * 4H

#define NBLK     64      // blocks per direction in lstm kernel
#define NBLK_TOT 128
#define FLAG_PAD 32      // one 128B line per flag

typedef unsigned long long ull;

// ---------------- device scratch (static, no allocation) ----------------
__device__ float g_xA[TOK * DINP];
__device__ float g_xB[TOK * DINP];
__device__ float g_pre[TOK * NPRE];
__device__ float g_pa[TOK * HID];
__device__ float g_pb[TOK * HID];
__device__ float    g_h[2 * 2 * HID * 4];          // [buf][dir][k][batch]
__device__ unsigned g_flag[NBLK_TOT * FLAG_PAD];   // per-block step counters

// ---------------- helpers ----------------
__device__ __forceinline__ float tanh_fast(float x) {
    float y;
    asm("tanh.approx.f32 %0, %1;" : "=f"(y) : "f"(x));
    return y;
}
__device__ __forceinline__ float sig_fast(float x) {
    return 0.5f * tanh_fast(0.5f * x) + 0.5f;
}
__device__ __forceinline__ ull pk2(float x) {
    ull d; asm("mov.b64 %0, {%1, %1};" : "=l"(d) : "f"(x)); return d;
}
__device__ __forceinline__ void fma2(ull& acc, ull a, ull b) {
    asm("fma.rn.f32x2 %0, %1, %2, %0;" : "+l"(acc) : "l"(a), "l"(b));
}
__device__ __forceinline__ void add2(ull& acc, ull a) {
    asm("add.rn.f32x2 %0, %0, %1;" : "+l"(acc) : "l"(a));
}
__device__ __forceinline__ float lo2(ull v) { return __uint_as_float((unsigned)v); }
__device__ __forceinline__ float hi2(ull v) { return __uint_as_float((unsigned)(v >> 32)); }
__device__ __forceinline__ unsigned ld_rlx(const unsigned* p) {
    unsigned v;
    asm volatile("ld.relaxed.gpu.global.b32 %0, [%1];" : "=r"(v) : "l"(p));
    return v;
}
__device__ __forceinline__ void st_rel(unsigned* p, unsigned v) {
    asm volatile("st.release.gpu.global.b32 [%0], %1;" :: "l"(p), "r"(v));
}
__device__ __forceinline__ void fence_acq() {
    asm volatile("fence.acq_rel.gpu;" ::: "memory");
}

__global__ void zero_flags_kernel() {
    g_flag[blockIdx.x * 256 + threadIdx.x] = 0u;
}

// ---------------- embedding gather + concat ----------------
__global__ __launch_bounds__(256) void embed_kernel(
    const int* __restrict__ sent, const int* __restrict__ pos,
    const float* __restrict__ emb)
{
    int gid = blockIdx.x * 256 + threadIdx.x;
    int token = gid >> 8;
    int q = gid & 255;
    const float4* src;
    if (q < 128) src = (const float4*)(emb + (size_t)sent[token] * HID) + q;
    else         src = (const float4*)(emb + (size_t)pos[token]  * HID) + (q - 128);
    ((float4*)g_xA)[gid] = *src;
}

// ---------------- fp32x2 SIMT GEMM: C[M,N] = A[M,K] * B[N,K]^T + bias(n) ----------------
__global__ __launch_bounds__(256) void gemm_kernel(
    const float* __restrict__ A, const float* __restrict__ B,
    float* __restrict__ C, int N, int K, int ldb,
    const float* __restrict__ bias1, const float* __restrict__ bias2)
{
    __shared__ float As[16][128];
    __shared__ float Bs[16][128];
    const int tid = threadIdx.x;
    const int bm = blockIdx.y << 7, bn = blockIdx.x << 7;
    const int row = tid >> 1;
    const int kq  = (tid & 1) << 3;
    const int tx = tid & 15, ty = tid >> 4;
    const int n0 = tx << 2, m0 = ty << 2;

    const float* Ap = A + (size_t)(bm + row) * K + kq;
    const float* Bp = B + (size_t)(bn + row) * ldb + kq;

    ull acc[8][4];
#pragma unroll
    for (int i = 0; i < 8; i++)
#pragma unroll
        for (int j = 0; j < 4; j++) acc[i][j] = 0ull;

    float4 a0v = *(const float4*)(Ap);
    float4 a1v = *(const float4*)(Ap + 4);
    float4 b0v = *(const float4*)(Bp);
    float4 b1v = *(const float4*)(Bp + 4);

    for (int k0 = 0; k0 < K; k0 += 16) {
        As[kq + 0][row] = a0v.x; As[kq + 1][row] = a0v.y;
        As[kq + 2][row] = a0v.z; As[kq + 3][row] = a0v.w;
        As[kq + 4][row] = a1v.x; As[kq + 5][row] = a1v.y;
        As[kq + 6][row] = a1v.z; As[kq + 7][row] = a1v.w;
        Bs[kq + 0][row] = b0v.x; Bs[kq + 1][row] = b0v.y;
        Bs[kq + 2][row] = b0v.z; Bs[kq + 3][row] = b0v.w;
        Bs[kq + 4][row] = b1v.x; Bs[kq + 5][row] = b1v.y;
        Bs[kq + 6][row] = b1v.z; Bs[kq + 7][row] = b1v.w;
        __syncthreads();

        if (k0 + 16 < K) {
            a0v = *(const float4*)(Ap + k0 + 16);
            a1v = *(const float4*)(Ap + k0 + 20);
            b0v = *(const float4*)(Bp + k0 + 16);
            b1v = *(const float4*)(Bp + k0 + 20);
        }

#pragma unroll
        for (int k = 0; k < 16; k++) {
            float4 am0 = *(const float4*)&As[k][m0];
            float4 am1 = *(const float4*)&As[k][m0 + 64];
            ulonglong2 bb0 = *(const ulonglong2*)&Bs[k][n0];
            ulonglong2 bb1 = *(const ulonglong2*)&Bs[k][n0 + 64];
            ull ad[8];
            ad[0] = pk2(am0.x); ad[1] = pk2(am0.y); ad[2] = pk2(am0.z); ad[3] = pk2(am0.w);
            ad[4] = pk2(am1.x); ad[5] = pk2(am1.y); ad[6] = pk2(am1.z); ad[7] = pk2(am1.w);
#pragma unroll
            for (int i = 0; i < 8; i++) {
                fma2(acc[i][0], ad[i], bb0.x);
                fma2(acc[i][1], ad[i], bb0.y);
                fma2(acc[i][2], ad[i], bb1.x);
                fma2(acc[i][3], ad[i], bb1.y);
            }
        }
        __syncthreads();
    }

    float bz[8];
#pragma unroll
    for (int jj = 0; jj < 8; jj++) {
        int n = bn + n0 + ((jj < 4) ? jj : 60 + jj);
        float bb = 0.0f;
        if (bias1) bb += bias1[n];
        if (bias2) bb += bias2[n];
        bz[jj] = bb;
    }
#pragma unroll
    for (int i = 0; i < 8; i++) {
        int m = bm + m0 + ((i < 4) ? i : 60 + i);
        float* Cr = C + (size_t)m * N + bn + n0;
        Cr[0]  = lo2(acc[i][0]) + bz[0];
        Cr[1]  = hi2(acc[i][0]) + bz[1];
        Cr[2]  = lo2(acc[i][1]) + bz[2];
        Cr[3]  = hi2(acc[i][1]) + bz[3];
        Cr[64] = lo2(acc[i][2]) + bz[4];
        Cr[65] = hi2(acc[i][2]) + bz[5];
        Cr[66] = lo2(acc[i][3]) + bz[6];
        Cr[67] = hi2(acc[i][3]) + bz[7];
    }
}

// ---------------- persistent bidirectional LSTM scan ----------------
// 128 blocks: [0,64) fwd, [64,128) bwd; each owns 8 hidden units (32 gate rows).
// Sync: per-producer padded flag; RELAXED polling + one acquire fence; producer
// publishes h-line (st.cg) then st.release flag (no threadfence).
// Matvec mapping r=tid>>3, kc=tid&7 puts a row's 8 partials in one warp ->
// butterfly-shuffle reduction, only 2 block barriers per step.
__global__ __launch_bounds__(256) void lstm_kernel(
    const float* __restrict__ pre,     // [TOK][4096], bias folded
    const float* __restrict__ whh,     // [2][2048][512] this layer
    const int* __restrict__ length,
    float* __restrict__ xout,          // [TOK][1024]
    int base)                          // l*SLEN
{
    __shared__ float4 hbufp[8][65];    // h chunks, padded: chunk kc entry kk
    __shared__ ull    gsum2[64];       // [r]: batch01, [32+r]: batch23

    const int tid = threadIdx.x;
    const int d   = blockIdx.x >> 6;
    const int blk = blockIdx.x & 63;
    const int u0  = blk * 8;
    const int r   = tid >> 3;          // local gate-row 0..31 (gate = r>>3, j = r&7)
    const int kc  = tid & 7;           // k-chunk 0..7

    // register-resident pre-packed W_hh slice
    ull wpk[64];
    {
        const float* wp = whh + (size_t)d * GHID * HID
                        + (size_t)((r >> 3) * HID + u0 + (r & 7)) * HID + kc * 64;
#pragma unroll
        for (int kk = 0; kk < 64; kk++) wpk[kk] = pk2(wp[kk]);
    }

    const bool is_w7 = (tid >= 224);
    const int lane = tid & 31;
    const int j7 = lane & 7, b7 = lane >> 3;
    float creg = 0.0f, hreg = 0.0f;
    const int len_b = is_w7 ? length[b7] : 0;

    unsigned* myflag = &g_flag[blockIdx.x * FLAG_PAD];
    const unsigned* dirflags = &g_flag[(d * NBLK) * FLAG_PAD];

    // gather targets for this thread: entries e0=2*tid, e1=2*tid+1 (k index = e)
    const int e0 = 2 * tid, e1 = 2 * tid + 1;
    float4* dst0 = &hbufp[e0 >> 6][e0 & 63];
    float4* dst1 = &hbufp[e1 >> 6][e1 & 63];

    for (int s = 0; s < SLEN; s++) {
        const int t = d ? (SLEN - 1 - s) : s;

        // warp7: prefetch pre-activations (independent of h)
        float pi = 0.f, pf = 0.f, pg = 0.f, po = 0.f;
        if (is_w7) {
            const float* pp = pre + (size_t)(b7 * SLEN + t) * NPRE + d * GHID + u0 + j7;
            pi = pp[0]; pf = pp[512]; pg = pp[1024]; po = pp[1536];
        }

        // poll producer (tid>>2) relaxed, fence once, gather own 2 float4s
        if (s == 0) {
            *dst0 = make_float4(0.f, 0.f, 0.f, 0.f);
            *dst1 = make_float4(0.f, 0.f, 0.f, 0.f);
        } else {
            const unsigned want = (unsigned)(base + s);
            const unsigned* fl = dirflags + (tid >> 2) * FLAG_PAD;
            while (ld_rlx(fl) < want) { }
            fence_acq();
            const float4* src = ((const float4*)g_h) + ((s & 1) * 2 + d) * 512 + e0;
            *dst0 = __ldcg(src);
            *dst1 = __ldcg(src + 1);
        }
        __syncthreads();   // SYNC1: hbuf ready (also orders prior gsum2 reads)

        // matvec: thread (r, kc) over k in [kc*64, kc*64+64)
        ull a01 = 0ull, a23 = 0ull;
        const float4* hc = &hbufp[kc][0];
#pragma unroll
        for (int kk = 0; kk < 64; kk++) {
            ulonglong2 hv = *(const ulonglong2*)&hc[kk];
            fma2(a01, wpk[kk], hv.x);
            fma2(a23, wpk[kk], hv.y);
        }
        // butterfly reduction over kc within warp (lanes differ only in low 3 bits)
#pragma unroll
        for (int m = 1; m < 8; m <<= 1) {
            add2(a01, __shfl_xor_sync(0xffffffffu, a01, m));
            add2(a23, __shfl_xor_sync(0xffffffffu, a23, m));
        }
        if (kc == 0) {
            gsum2[r]      = a01;
            gsum2[32 + r] = a23;
        }
        __syncthreads();   // SYNC2: gate sums ready

        // warp7: activation + publish (runs while other warps start next poll)
        if (is_w7) {
            const float* gs = (const float*)gsum2;
            const int bb = (b7 >> 1) * 64 + (b7 & 1);
            float gi = pi + gs[bb + (0 * 8 + j7) * 2];
            float gf = pf + gs[bb + (1 * 8 + j7) * 2];
            float gg = pg + gs[bb + (2 * 8 + j7) * 2];
            float go = po + gs[bb + (3 * 8 + j7) * 2];
            float cn = sig_fast(gf) * creg + sig_fast(gi) * tanh_fast(gg);
            float hn = sig_fast(go) * tanh_fast(cn);
            bool m = (t < len_b);
            if (m) { creg = cn; hreg = hn; }
            // publish h (buffer (s+1)&1): 32 consecutive floats = one 128B line
            __stcg(&((float*)g_h)[((((s + 1) & 1) * 2 + d) * 512 + u0 + j7) * 4 + b7], hreg);
            __syncwarp();
            if (lane == 0) st_rel(myflag, (unsigned)(base + s + 1));
            // xout after release: off the critical path
            xout[(size_t)(b7 * SLEN + t) * DINP + d * HID + u0 + j7] = m ? hn : 0.0f;
        }
    }
}

// ---------------- score: out[b,s,t] = b2 + sum_h w2[h]*tanh(pa[b,s,h]+pbb[b,t,h]) ----------------
__global__ __launch_bounds__(256) void score_kernel(
    const float* __restrict__ pa, const float* __restrict__ pb,
    const float* __restrict__ w2, const float* __restrict__ b2,
    float* __restrict__ out)
{
    extern __shared__ float sm[];
    float* paT = sm;                 // [512][17]
    float* pbT = sm + 512 * 17;
    float* w2s = pbT + 512 * 17;     // [512]

    const int tid = threadIdx.x;
    const int btt = blockIdx.x, bss = blockIdx.y, b = blockIdx.z;

    for (int idx = tid; idx < 16 * 512; idx += 256) {
        int row = idx >> 9, h = idx & 511;
        paT[h * 17 + row] = pa[(size_t)(b * SLEN + bss * 16 + row) * HID + h];
        pbT[h * 17 + row] = pb[(size_t)(b * SLEN + btt * 16 + row) * HID + h];
    }
    for (int idx = tid; idx < 512; idx += 256) w2s[idx] = w2[idx];
    __syncthreads();

    const int si = tid & 15, ti = tid >> 4;
    float acc = 0.0f;
#pragma unroll 8
    for (int h = 0; h < 512; h++) {
        float x = paT[h * 17 + si] + pbT[h * 17 + ti];
        acc = fmaf(w2s[h], tanh_fast(x), acc);
    }
    out[(size_t)(b * SLEN + bss * 16 + si) * SLEN + btt * 16 + ti] = acc + b2[0];
}

// ---------------- launch ----------------
extern "C" void kernel_launch(void* const* d_in, const int* in_sizes, int n_in,
                              void* d_out, int out_size)
{
    const int*   sent   = (const int*)d_in[0];
    const int*   pos    = (const int*)d_in[1];
    const int*   length = (const int*)d_in[2];
    const float* emb    = (const float*)d_in[3];
    const float* w_ih   = (const float*)d_in[4];
    const float* w_hh   = (const float*)d_in[5];
    const float* b_ih   = (const float*)d_in[6];
    const float* b_hh   = (const float*)d_in[7];
    const float* w1     = (const float*)d_in[8];
    const float* b1     = (const float*)d_in[9];
    const float* w2     = (const float*)d_in[10];
    const float* b2     = (const float*)d_in[11];
    float* out = (float*)d_out;

    const int SCORE_SMEM = 2 * 512 * 17 * 4 + 512 * 4;
    cudaFuncSetAttribute(score_kernel, cudaFuncAttributeMaxDynamicSharedMemorySize, SCORE_SMEM);

    float *xA, *xB, *prep, *pap, *pbp;
    cudaGetSymbolAddress((void**)&xA,   g_xA);
    cudaGetSymbolAddress((void**)&xB,   g_xB);
    cudaGetSymbolAddress((void**)&prep, g_pre);
    cudaGetSymbolAddress((void**)&pap,  g_pa);
    cudaGetSymbolAddress((void**)&pbp,  g_pb);

    zero_flags_kernel<<<NBLK_TOT * FLAG_PAD / 256, 256>>>();
    embed_kernel<<<1024, 256>>>(sent, pos, emb);

    for (int l = 0; l < 2; l++) {
        const float* Ain = l ? xB : xA;
        float* Xout      = l ? xA : xB;
        gemm_kernel<<<dim3(NPRE / 128, TOK / 128), 256>>>(
            Ain, w_ih + (size_t)l * NPRE * DINP, prep,
            NPRE, DINP, DINP, b_ih + l * NPRE, b_hh + l * NPRE);
        lstm_kernel<<<NBLK_TOT, 256>>>(
            prep, w_hh + (size_t)l * 2 * GHID * HID, length, Xout, l * SLEN);
    }

    gemm_kernel<<<dim3(HID / 128, TOK / 128), 256>>>(
        xA, w1,        pap, HID, DINP, 2048, nullptr, nullptr);
    gemm_kernel<<<dim3(HID / 128, TOK / 128), 256>>>(
        xA, w1 + 1024, pbp, HID, DINP, 2048, b1, nullptr);

    score_kernel<<<dim3(16, 16, 4), 256, SCORE_SMEM>>>(pap, pbp, w2, b2, out);
}

// round 9
// speedup vs baseline: 1.3439x; 1.3439x over previous
#include <cuda_runtime.h>
#include <math.h>
#include <stdint.h>

#define TOK   1024   // B*S
#define SLEN  256
#define BATCH 4
#define HID   512
#define DINP  1024
#define GHID  2048
#define NPRE  4096   // 2 dirs * 4H

#define NBLK     64      // blocks per direction in lstm kernel
#define NBLK_TOT 128
#define FLAG_PAD 32      // one 128B line per flag

typedef unsigned long long ull;

// ---------------- device scratch (static, no allocation) ----------------
__device__ float g_xA[TOK * DINP];
__device__ float g_xB[TOK * DINP];
__device__ float g_pre[TOK * NPRE];
__device__ float g_pa[TOK * HID];
__device__ float g_pb[TOK * HID];
__device__ float    g_h[2 * 2 * HID * 4];          // [buf][dir][k][batch]
__device__ unsigned g_flag[NBLK_TOT * FLAG_PAD];   // per-block step counters

// ---------------- helpers ----------------
__device__ __forceinline__ float tanh_fast(float x) {
    float y;
    asm("tanh.approx.f32 %0, %1;" : "=f"(y) : "f"(x));
    return y;
}
__device__ __forceinline__ float sig_fast(float x) {
    return 0.5f * tanh_fast(0.5f * x) + 0.5f;
}
__device__ __forceinline__ ull pk2(float x) {
    ull d; asm("mov.b64 %0, {%1, %1};" : "=l"(d) : "f"(x)); return d;
}
__device__ __forceinline__ void fma2(ull& acc, ull a, ull b) {
    asm("fma.rn.f32x2 %0, %1, %2, %0;" : "+l"(acc) : "l"(a), "l"(b));
}
__device__ __forceinline__ void add2(ull& acc, ull a) {
    asm("add.rn.f32x2 %0, %0, %1;" : "+l"(acc) : "l"(a));
}
__device__ __forceinline__ float lo2(ull v) { return __uint_as_float((unsigned)v); }
__device__ __forceinline__ float hi2(ull v) { return __uint_as_float((unsigned)(v >> 32)); }
__device__ __forceinline__ unsigned ld_acq(const unsigned* p) {
    unsigned v;
    asm volatile("ld.acquire.gpu.global.b32 %0, [%1];" : "=r"(v) : "l"(p));
    return v;
}
__device__ __forceinline__ void st_rel(unsigned* p, unsigned v) {
    asm volatile("st.release.gpu.global.b32 [%0], %1;" :: "l"(p), "r"(v));
}
__device__ __forceinline__ void backoff() {
    asm volatile("nanosleep.u32 100;");
}

__global__ void zero_flags_kernel() {
    g_flag[blockIdx.x * 256 + threadIdx.x] = 0u;
}

// ---------------- embedding gather + concat ----------------
__global__ __launch_bounds__(256) void embed_kernel(
    const int* __restrict__ sent, const int* __restrict__ pos,
    const float* __restrict__ emb)
{
    int gid = blockIdx.x * 256 + threadIdx.x;
    int token = gid >> 8;
    int q = gid & 255;
    const float4* src;
    if (q < 128) src = (const float4*)(emb + (size_t)sent[token] * HID) + q;
    else         src = (const float4*)(emb + (size_t)pos[token]  * HID) + (q - 128);
    ((float4*)g_xA)[gid] = *src;
}

// ---------------- fp32x2 SIMT GEMM: C[M,N] = A[M,K] * B[N,K]^T + bias(n) ----------------
__global__ __launch_bounds__(256) void gemm_kernel(
    const float* __restrict__ A, const float* __restrict__ B,
    float* __restrict__ C, int N, int K, int ldb,
    const float* __restrict__ bias1, const float* __restrict__ bias2)
{
    __shared__ float As[16][128];
    __shared__ float Bs[16][128];
    const int tid = threadIdx.x;
    const int bm = blockIdx.y << 7, bn = blockIdx.x << 7;
    const int row = tid >> 1;
    const int kq  = (tid & 1) << 3;
    const int tx = tid & 15, ty = tid >> 4;
    const int n0 = tx << 2, m0 = ty << 2;

    const float* Ap = A + (size_t)(bm + row) * K + kq;
    const float* Bp = B + (size_t)(bn + row) * ldb + kq;

    ull acc[8][4];
#pragma unroll
    for (int i = 0; i < 8; i++)
#pragma unroll
        for (int j = 0; j < 4; j++) acc[i][j] = 0ull;

    float4 a0v = *(const float4*)(Ap);
    float4 a1v = *(const float4*)(Ap + 4);
    float4 b0v = *(const float4*)(Bp);
    float4 b1v = *(const float4*)(Bp + 4);

    for (int k0 = 0; k0 < K; k0 += 16) {
        As[kq + 0][row] = a0v.x; As[kq + 1][row] = a0v.y;
        As[kq + 2][row] = a0v.z; As[kq + 3][row] = a0v.w;
        As[kq + 4][row] = a1v.x; As[kq + 5][row] = a1v.y;
        As[kq + 6][row] = a1v.z; As[kq + 7][row] = a1v.w;
        Bs[kq + 0][row] = b0v.x; Bs[kq + 1][row] = b0v.y;
        Bs[kq + 2][row] = b0v.z; Bs[kq + 3][row] = b0v.w;
        Bs[kq + 4][row] = b1v.x; Bs[kq + 5][row] = b1v.y;
        Bs[kq + 6][row] = b1v.z; Bs[kq + 7][row] = b1v.w;
        __syncthreads();

        if (k0 + 16 < K) {
            a0v = *(const float4*)(Ap + k0 + 16);
            a1v = *(const float4*)(Ap + k0 + 20);
            b0v = *(const float4*)(Bp + k0 + 16);
            b1v = *(const float4*)(Bp + k0 + 20);
        }

#pragma unroll
        for (int k = 0; k < 16; k++) {
            float4 am0 = *(const float4*)&As[k][m0];
            float4 am1 = *(const float4*)&As[k][m0 + 64];
            ulonglong2 bb0 = *(const ulonglong2*)&Bs[k][n0];
            ulonglong2 bb1 = *(const ulonglong2*)&Bs[k][n0 + 64];
            ull ad[8];
            ad[0] = pk2(am0.x); ad[1] = pk2(am0.y); ad[2] = pk2(am0.z); ad[3] = pk2(am0.w);
            ad[4] = pk2(am1.x); ad[5] = pk2(am1.y); ad[6] = pk2(am1.z); ad[7] = pk2(am1.w);
#pragma unroll
            for (int i = 0; i < 8; i++) {
                fma2(acc[i][0], ad[i], bb0.x);
                fma2(acc[i][1], ad[i], bb0.y);
                fma2(acc[i][2], ad[i], bb1.x);
                fma2(acc[i][3], ad[i], bb1.y);
            }
        }
        __syncthreads();
    }

    float bz[8];
#pragma unroll
    for (int jj = 0; jj < 8; jj++) {
        int n = bn + n0 + ((jj < 4) ? jj : 60 + jj);
        float bb = 0.0f;
        if (bias1) bb += bias1[n];
        if (bias2) bb += bias2[n];
        bz[jj] = bb;
    }
#pragma unroll
    for (int i = 0; i < 8; i++) {
        int m = bm + m0 + ((i < 4) ? i : 60 + i);
        float* Cr = C + (size_t)m * N + bn + n0;
        Cr[0]  = lo2(acc[i][0]) + bz[0];
        Cr[1]  = hi2(acc[i][0]) + bz[1];
        Cr[2]  = lo2(acc[i][1]) + bz[2];
        Cr[3]  = hi2(acc[i][1]) + bz[3];
        Cr[64] = lo2(acc[i][2]) + bz[4];
        Cr[65] = hi2(acc[i][2]) + bz[5];
        Cr[66] = lo2(acc[i][3]) + bz[6];
        Cr[67] = hi2(acc[i][3]) + bz[7];
    }
}

// ---------------- persistent bidirectional LSTM scan (R7 base + poll backoff) ----------------
// 128 blocks: [0,64) fwd, [64,128) bwd; each owns 8 hidden units (32 gate rows).
// Per-producer padded flag, acquire-poll with nanosleep backoff (anti poll-storm);
// h double-buffered in g_h; xout store after flag release.
__global__ __launch_bounds__(256) void lstm_kernel(
    const float* __restrict__ pre,     // [TOK][4096], bias folded
    const float* __restrict__ whh,     // [2][2048][512] this layer
    const int* __restrict__ length,
    float* __restrict__ xout,          // [TOK][1024]
    int base)                          // l*SLEN
{
    __shared__ float4 hbuf[512];       // h[k][4 batch]
    __shared__ ull    red2[512];       // matvec partials (packed batch pairs)
    __shared__ ull    gsum2[64];       // reduced gates  (packed batch pairs)

    const int tid = threadIdx.x;
    const int d   = blockIdx.x >> 6;
    const int blk = blockIdx.x & 63;
    const int u0  = blk * 8;
    const int r   = tid & 31;          // local gate-row (gate = r>>3, j = r&7)
    const int kc  = tid >> 5;          // k-chunk 0..7

    // register-resident pre-packed W_hh slice
    ull wpk[64];
    {
        const float* wp = whh + (size_t)d * GHID * HID
                        + (size_t)((r >> 3) * HID + u0 + (r & 7)) * HID + kc * 64;
#pragma unroll
        for (int kk = 0; kk < 64; kk++) wpk[kk] = pk2(wp[kk]);
    }

    const bool is_w7 = (tid >= 224);
    const int lane = tid & 31;
    const int j7 = lane & 7, b7 = lane >> 3;
    float creg = 0.0f, hreg = 0.0f;
    const int len_b = is_w7 ? length[b7] : 0;

    unsigned* myflag = &g_flag[blockIdx.x * FLAG_PAD];
    const unsigned* dirflags = &g_flag[(d * NBLK) * FLAG_PAD];

    for (int s = 0; s < SLEN; s++) {
        const int t = d ? (SLEN - 1 - s) : s;

        // warp7: prefetch pre-activations for owned gates (independent of h)
        float pi = 0.f, pf = 0.f, pg = 0.f, po = 0.f;
        if (is_w7) {
            const float* pp = pre + (size_t)(b7 * SLEN + t) * NPRE + d * GHID + u0 + j7;
            pi = pp[0]; pf = pp[512]; pg = pp[1024]; po = pp[1536];
        }

        // all 256 threads: poll producer (tid>>2)'s flag, gather own 2 float4s
        if (s == 0) {
            hbuf[2 * tid]     = make_float4(0.f, 0.f, 0.f, 0.f);
            hbuf[2 * tid + 1] = make_float4(0.f, 0.f, 0.f, 0.f);
        } else {
            const unsigned want = (unsigned)(base + s);
            const unsigned* fl = dirflags + (tid >> 2) * FLAG_PAD;
            // first check free; then backoff-poll to avoid LTS queue storm
            if (ld_acq(fl) < want) {
                do { backoff(); } while (ld_acq(fl) < want);
            }
            const float4* src = ((const float4*)g_h) + ((s & 1) * 2 + d) * 512 + 2 * tid;
            hbuf[2 * tid]     = __ldcg(src);
            hbuf[2 * tid + 1] = __ldcg(src + 1);
        }
        __syncthreads();   // S1: hbuf ready

        // matvec: thread (r, kc), 64 k per thread, batch-packed f32x2
        ull a01 = 0ull, a23 = 0ull;
        const ulonglong2* hp = (const ulonglong2*)(hbuf + kc * 64);
#pragma unroll
        for (int kk = 0; kk < 64; kk++) {
            ulonglong2 hv = hp[kk];          // LDS.128 broadcast within warp
            fma2(a01, wpk[kk], hv.x);
            fma2(a23, wpk[kk], hv.y);
        }
        red2[tid] = a01;
        red2[256 + tid] = a23;
        __syncthreads();   // S2

        // packed 8-way reduction: 64 threads
        if (tid < 64) {
            const int rr = tid & 31, half = tid >> 5;
            const ull* rp = red2 + half * 256 + rr;
            ull sum = rp[0];
#pragma unroll
            for (int q = 1; q < 8; q++) add2(sum, rp[q * 32]);
            gsum2[half * 32 + rr] = sum;
        }
        __syncthreads();   // S3

        // warp7: activation + publish (runs while other warps start next poll)
        if (is_w7) {
            const float* gs = (const float*)gsum2;
            const int bb = (b7 >> 1) * 64 + (b7 & 1);
            float gi = pi + gs[bb + (0 * 8 + j7) * 2];
            float gf = pf + gs[bb + (1 * 8 + j7) * 2];
            float gg = pg + gs[bb + (2 * 8 + j7) * 2];
            float go = po + gs[bb + (3 * 8 + j7) * 2];
            float cn = sig_fast(gf) * creg + sig_fast(gi) * tanh_fast(gg);
            float hn = sig_fast(go) * tanh_fast(cn);
            bool m = (t < len_b);
            if (m) { creg = cn; hreg = hn; }
            // publish h (buffer (s+1)&1): 32 consecutive floats = one 128B line
            __stcg(&((float*)g_h)[((((s + 1) & 1) * 2 + d) * 512 + u0 + j7) * 4 + b7], hreg);
            __syncwarp();
            __threadfence();                  // drains the h-line store
            if (lane == 0) st_rel(myflag, (unsigned)(base + s + 1));
            // xout after release: off the critical path
            xout[(size_t)(b7 * SLEN + t) * DINP + d * HID + u0 + j7] = m ? hn : 0.0f;
        }
    }
}

// ---------------- score: out[b,s,t] = b2 + sum_h w2[h]*tanh(pa[b,s,h]+pbb[b,t,h]) ----------------
__global__ __launch_bounds__(256) void score_kernel(
    const float* __restrict__ pa, const float* __restrict__ pb,
    const float* __restrict__ w2, const float* __restrict__ b2,
    float* __restrict__ out)
{
    extern __shared__ float sm[];
    float* paT = sm;                 // [512][17]
    float* pbT = sm + 512 * 17;
    float* w2s = pbT + 512 * 17;     // [512]

    const int tid = threadIdx.x;
    const int btt = blockIdx.x, bss = blockIdx.y, b = blockIdx.z;

    for (int idx = tid; idx < 16 * 512; idx += 256) {
        int row = idx >> 9, h = idx & 511;
        paT[h * 17 + row] = pa[(size_t)(b * SLEN + bss * 16 + row) * HID + h];
        pbT[h * 17 + row] = pb[(size_t)(b * SLEN + btt * 16 + row) * HID + h];
    }
    for (int idx = tid; idx < 512; idx += 256) w2s[idx] = w2[idx];
    __syncthreads();

    const int si = tid & 15, ti = tid >> 4;
    float acc = 0.0f;
#pragma unroll 8
    for (int h = 0; h < 512; h++) {
        float x = paT[h * 17 + si] + pbT[h * 17 + ti];
        acc = fmaf(w2s[h], tanh_fast(x), acc);
    }
    out[(size_t)(b * SLEN + bss * 16 + si) * SLEN + btt * 16 + ti] = acc + b2[0];
}

// ---------------- launch ----------------
extern "C" void kernel_launch(void* const* d_in, const int* in_sizes, int n_in,
                              void* d_out, int out_size)
{
    const int*   sent   = (const int*)d_in[0];
    const int*   pos    = (const int*)d_in[1];
    const int*   length = (const int*)d_in[2];
    const float* emb    = (const float*)d_in[3];
    const float* w_ih   = (const float*)d_in[4];
    const float* w_hh   = (const float*)d_in[5];
    const float* b_ih   = (const float*)d_in[6];
    const float* b_hh   = (const float*)d_in[7];
    const float* w1     = (const float*)d_in[8];
    const float* b1     = (const float*)d_in[9];
    const float* w2     = (const float*)d_in[10];
    const float* b2     = (const float*)d_in[11];
    float* out = (float*)d_out;

    const int SCORE_SMEM = 2 * 512 * 17 * 4 + 512 * 4;
    cudaFuncSetAttribute(score_kernel, cudaFuncAttributeMaxDynamicSharedMemorySize, SCORE_SMEM);

    float *xA, *xB, *prep, *pap, *pbp;
    cudaGetSymbolAddress((void**)&xA,   g_xA);
    cudaGetSymbolAddress((void**)&xB,   g_xB);
    cudaGetSymbolAddress((void**)&prep, g_pre);
    cudaGetSymbolAddress((void**)&pap,  g_pa);
    cudaGetSymbolAddress((void**)&pbp,  g_pb);

    zero_flags_kernel<<<NBLK_TOT * FLAG_PAD / 256, 256>>>();
    embed_kernel<<<1024, 256>>>(sent, pos, emb);

    for (int l = 0; l < 2; l++) {
        const float* Ain = l ? xB : xA;
        float* Xout      = l ? xA : xB;
        gemm_kernel<<<dim3(NPRE / 128, TOK / 128), 256>>>(
            Ain, w_ih + (size_t)l * NPRE * DINP, prep,
            NPRE, DINP, DINP, b_ih + l * NPRE, b_hh + l * NPRE);
        lstm_kernel<<<NBLK_TOT, 256>>>(
            prep, w_hh + (size_t)l * 2 * GHID * HID, length, Xout, l * SLEN);
    }

    gemm_kernel<<<dim3(HID / 128, TOK / 128), 256>>>(
        xA, w1,        pap, HID, DINP, 2048, nullptr, nullptr);
    gemm_kernel<<<dim3(HID / 128, TOK / 128), 256>>>(
        xA, w1 + 1024, pbp, HID, DINP, 2048, b1, nullptr);

    score_kernel<<<dim3(16, 16, 4), 256, SCORE_SMEM>>>(pap, pbp, w2, b2, out);
}

// round 10
// speedup vs baseline: 1.5239x; 1.1340x over previous
#include <cuda_runtime.h>
#include <math.h>
#include <stdint.h>

#define TOK   1024   // B*S
#define SLEN  256
#define BATCH 4
#define HID   512
#define DINP  1024
#define GHID  2048
#define NPRE  4096   // 2 dirs * 4H

#define NBLK     64      // blocks per direction in lstm kernel
#define NBLK_TOT 128
#define FLAG_PAD 32      // one 128B line per flag

typedef unsigned long long ull;

// ---------------- device scratch (static, no allocation) ----------------
__device__ float g_xA[TOK * DINP];
__device__ float g_xB[TOK * DINP];
__device__ float g_pre[TOK * NPRE];
__device__ float g_pa[TOK * HID];
__device__ float g_pb[TOK * HID];
__device__ float    g_h[2 * 2 * HID * 4];          // [buf][dir][k][batch]
__device__ unsigned g_flag[NBLK_TOT * FLAG_PAD];   // per-block step counters

// ---------------- helpers ----------------
__device__ __forceinline__ float tanh_fast(float x) {
    float y;
    asm("tanh.approx.f32 %0, %1;" : "=f"(y) : "f"(x));
    return y;
}
__device__ __forceinline__ float sig_fast(float x) {
    return 0.5f * tanh_fast(0.5f * x) + 0.5f;
}
__device__ __forceinline__ ull pk2(float x) {
    ull d; asm("mov.b64 %0, {%1, %1};" : "=l"(d) : "f"(x)); return d;
}
__device__ __forceinline__ void fma2(ull& acc, ull a, ull b) {
    asm("fma.rn.f32x2 %0, %1, %2, %0;" : "+l"(acc) : "l"(a), "l"(b));
}
__device__ __forceinline__ void add2(ull& acc, ull a) {
    asm("add.rn.f32x2 %0, %0, %1;" : "+l"(acc) : "l"(a));
}
__device__ __forceinline__ float lo2(ull v) { return __uint_as_float((unsigned)v); }
__device__ __forceinline__ float hi2(ull v) { return __uint_as_float((unsigned)(v >> 32)); }
__device__ __forceinline__ unsigned ld_acq(const unsigned* p) {
    unsigned v;
    asm volatile("ld.acquire.gpu.global.b32 %0, [%1];" : "=r"(v) : "l"(p));
    return v;
}
__device__ __forceinline__ void st_rel(unsigned* p, unsigned v) {
    asm volatile("st.release.gpu.global.b32 [%0], %1;" :: "l"(p), "r"(v));
}
__device__ __forceinline__ void backoff() {
    asm volatile("nanosleep.u32 100;");
}

__global__ void zero_flags_kernel() {
    g_flag[blockIdx.x * 256 + threadIdx.x] = 0u;
}

// ---------------- embedding gather + concat ----------------
__global__ __launch_bounds__(256) void embed_kernel(
    const int* __restrict__ sent, const int* __restrict__ pos,
    const float* __restrict__ emb)
{
    int gid = blockIdx.x * 256 + threadIdx.x;
    int token = gid >> 8;
    int q = gid & 255;
    const float4* src;
    if (q < 128) src = (const float4*)(emb + (size_t)sent[token] * HID) + q;
    else         src = (const float4*)(emb + (size_t)pos[token]  * HID) + (q - 128);
    ((float4*)g_xA)[gid] = *src;
}

// ---------------- fp32x2 SIMT GEMM: C[M,N] = A[M,K] * B[N,K]^T + bias(n) ----------------
__global__ __launch_bounds__(256) void gemm_kernel(
    const float* __restrict__ A, const float* __restrict__ B,
    float* __restrict__ C, int N, int K, int ldb,
    const float* __restrict__ bias1, const float* __restrict__ bias2)
{
    __shared__ float As[16][128];
    __shared__ float Bs[16][128];
    const int tid = threadIdx.x;
    const int bm = blockIdx.y << 7, bn = blockIdx.x << 7;
    const int row = tid >> 1;
    const int kq  = (tid & 1) << 3;
    const int tx = tid & 15, ty = tid >> 4;
    const int n0 = tx << 2, m0 = ty << 2;

    const float* Ap = A + (size_t)(bm + row) * K + kq;
    const float* Bp = B + (size_t)(bn + row) * ldb + kq;

    ull acc[8][4];
#pragma unroll
    for (int i = 0; i < 8; i++)
#pragma unroll
        for (int j = 0; j < 4; j++) acc[i][j] = 0ull;

    float4 a0v = *(const float4*)(Ap);
    float4 a1v = *(const float4*)(Ap + 4);
    float4 b0v = *(const float4*)(Bp);
    float4 b1v = *(const float4*)(Bp + 4);

    for (int k0 = 0; k0 < K; k0 += 16) {
        As[kq + 0][row] = a0v.x; As[kq + 1][row] = a0v.y;
        As[kq + 2][row] = a0v.z; As[kq + 3][row] = a0v.w;
        As[kq + 4][row] = a1v.x; As[kq + 5][row] = a1v.y;
        As[kq + 6][row] = a1v.z; As[kq + 7][row] = a1v.w;
        Bs[kq + 0][row] = b0v.x; Bs[kq + 1][row] = b0v.y;
        Bs[kq + 2][row] = b0v.z; Bs[kq + 3][row] = b0v.w;
        Bs[kq + 4][row] = b1v.x; Bs[kq + 5][row] = b1v.y;
        Bs[kq + 6][row] = b1v.z; Bs[kq + 7][row] = b1v.w;
        __syncthreads();

        if (k0 + 16 < K) {
            a0v = *(const float4*)(Ap + k0 + 16);
            a1v = *(const float4*)(Ap + k0 + 20);
            b0v = *(const float4*)(Bp + k0 + 16);
            b1v = *(const float4*)(Bp + k0 + 20);
        }

#pragma unroll
        for (int k = 0; k < 16; k++) {
            float4 am0 = *(const float4*)&As[k][m0];
            float4 am1 = *(const float4*)&As[k][m0 + 64];
            ulonglong2 bb0 = *(const ulonglong2*)&Bs[k][n0];
            ulonglong2 bb1 = *(const ulonglong2*)&Bs[k][n0 + 64];
            ull ad[8];
            ad[0] = pk2(am0.x); ad[1] = pk2(am0.y); ad[2] = pk2(am0.z); ad[3] = pk2(am0.w);
            ad[4] = pk2(am1.x); ad[5] = pk2(am1.y); ad[6] = pk2(am1.z); ad[7] = pk2(am1.w);
#pragma unroll
            for (int i = 0; i < 8; i++) {
                fma2(acc[i][0], ad[i], bb0.x);
                fma2(acc[i][1], ad[i], bb0.y);
                fma2(acc[i][2], ad[i], bb1.x);
                fma2(acc[i][3], ad[i], bb1.y);
            }
        }
        __syncthreads();
    }

    float bz[8];
#pragma unroll
    for (int jj = 0; jj < 8; jj++) {
        int n = bn + n0 + ((jj < 4) ? jj : 60 + jj);
        float bb = 0.0f;
        if (bias1) bb += bias1[n];
        if (bias2) bb += bias2[n];
        bz[jj] = bb;
    }
#pragma unroll
    for (int i = 0; i < 8; i++) {
        int m = bm + m0 + ((i < 4) ? i : 60 + i);
        float* Cr = C + (size_t)m * N + bn + n0;
        Cr[0]  = lo2(acc[i][0]) + bz[0];
        Cr[1]  = hi2(acc[i][0]) + bz[1];
        Cr[2]  = lo2(acc[i][1]) + bz[2];
        Cr[3]  = hi2(acc[i][1]) + bz[3];
        Cr[64] = lo2(acc[i][2]) + bz[4];
        Cr[65] = hi2(acc[i][2]) + bz[5];
        Cr[66] = lo2(acc[i][3]) + bz[6];
        Cr[67] = hi2(acc[i][3]) + bz[7];
    }
}

// ---------------- persistent bidirectional LSTM scan (R9 base, fence removed) ----------------
// 128 blocks: [0,64) fwd, [64,128) bwd; each owns 8 hidden units (32 gate rows).
// Per-producer padded flag, acquire-poll with nanosleep backoff; h double-buffered.
// Publish ordering: lanes' st.cg h-line -> __syncwarp (warp-scope memory order)
// -> lane0 st.release.gpu flag. Release alone carries the ordering; no MEMBAR.
__global__ __launch_bounds__(256) void lstm_kernel(
    const float* __restrict__ pre,     // [TOK][4096], bias folded
    const float* __restrict__ whh,     // [2][2048][512] this layer
    const int* __restrict__ length,
    float* __restrict__ xout,          // [TOK][1024]
    int base)                          // l*SLEN
{
    __shared__ float4 hbuf[512];       // h[k][4 batch]
    __shared__ ull    red2[512];       // matvec partials (packed batch pairs)
    __shared__ ull    gsum2[64];       // reduced gates  (packed batch pairs)

    const int tid = threadIdx.x;
    const int d   = blockIdx.x >> 6;
    const int blk = blockIdx.x & 63;
    const int u0  = blk * 8;
    const int r   = tid & 31;          // local gate-row (gate = r>>3, j = r&7)
    const int kc  = tid >> 5;          // k-chunk 0..7

    // register-resident pre-packed W_hh slice
    ull wpk[64];
    {
        const float* wp = whh + (size_t)d * GHID * HID
                        + (size_t)((r >> 3) * HID + u0 + (r & 7)) * HID + kc * 64;
#pragma unroll
        for (int kk = 0; kk < 64; kk++) wpk[kk] = pk2(wp[kk]);
    }

    const bool is_w7 = (tid >= 224);
    const int lane = tid & 31;
    const int j7 = lane & 7, b7 = lane >> 3;
    float creg = 0.0f, hreg = 0.0f;
    const int len_b = is_w7 ? length[b7] : 0;

    unsigned* myflag = &g_flag[blockIdx.x * FLAG_PAD];
    const unsigned* dirflags = &g_flag[(d * NBLK) * FLAG_PAD];

    for (int s = 0; s < SLEN; s++) {
        const int t = d ? (SLEN - 1 - s) : s;

        // warp7: prefetch pre-activations for owned gates (independent of h)
        float pi = 0.f, pf = 0.f, pg = 0.f, po = 0.f;
        if (is_w7) {
            const float* pp = pre + (size_t)(b7 * SLEN + t) * NPRE + d * GHID + u0 + j7;
            pi = pp[0]; pf = pp[512]; pg = pp[1024]; po = pp[1536];
        }

        // all 256 threads: poll producer (tid>>2)'s flag, gather own 2 float4s
        if (s == 0) {
            hbuf[2 * tid]     = make_float4(0.f, 0.f, 0.f, 0.f);
            hbuf[2 * tid + 1] = make_float4(0.f, 0.f, 0.f, 0.f);
        } else {
            const unsigned want = (unsigned)(base + s);
            const unsigned* fl = dirflags + (tid >> 2) * FLAG_PAD;
            // first check free; then backoff-poll to avoid LTS queue storm
            if (ld_acq(fl) < want) {
                do { backoff(); } while (ld_acq(fl) < want);
            }
            const float4* src = ((const float4*)g_h) + ((s & 1) * 2 + d) * 512 + 2 * tid;
            hbuf[2 * tid]     = __ldcg(src);
            hbuf[2 * tid + 1] = __ldcg(src + 1);
        }
        __syncthreads();   // S1: hbuf ready

        // matvec: thread (r, kc), 64 k per thread, batch-packed f32x2
        ull a01 = 0ull, a23 = 0ull;
        const ulonglong2* hp = (const ulonglong2*)(hbuf + kc * 64);
#pragma unroll
        for (int kk = 0; kk < 64; kk++) {
            ulonglong2 hv = hp[kk];          // LDS.128 broadcast within warp
            fma2(a01, wpk[kk], hv.x);
            fma2(a23, wpk[kk], hv.y);
        }
        red2[tid] = a01;
        red2[256 + tid] = a23;
        __syncthreads();   // S2

        // packed 8-way reduction: 64 threads
        if (tid < 64) {
            const int rr = tid & 31, half = tid >> 5;
            const ull* rp = red2 + half * 256 + rr;
            ull sum = rp[0];
#pragma unroll
            for (int q = 1; q < 8; q++) add2(sum, rp[q * 32]);
            gsum2[half * 32 + rr] = sum;
        }
        __syncthreads();   // S3

        // warp7: activation + publish (runs while other warps start next poll)
        if (is_w7) {
            const float* gs = (const float*)gsum2;
            const int bb = (b7 >> 1) * 64 + (b7 & 1);
            float gi = pi + gs[bb + (0 * 8 + j7) * 2];
            float gf = pf + gs[bb + (1 * 8 + j7) * 2];
            float gg = pg + gs[bb + (2 * 8 + j7) * 2];
            float go = po + gs[bb + (3 * 8 + j7) * 2];
            float cn = sig_fast(gf) * creg + sig_fast(gi) * tanh_fast(gg);
            float hn = sig_fast(go) * tanh_fast(cn);
            bool m = (t < len_b);
            if (m) { creg = cn; hreg = hn; }
            // publish h (buffer (s+1)&1): 32 consecutive floats = one 128B line
            __stcg(&((float*)g_h)[((((s + 1) & 1) * 2 + d) * 512 + u0 + j7) * 4 + b7], hreg);
            __syncwarp();                     // warp-scope memory order: h-line HB release
            if (lane == 0) st_rel(myflag, (unsigned)(base + s + 1));
            // xout after release: off the critical path
            xout[(size_t)(b7 * SLEN + t) * DINP + d * HID + u0 + j7] = m ? hn : 0.0f;
        }
    }
}

// ---------------- score: out[b,s,t] = b2 + sum_h w2[h]*tanh(pa[b,s,h]+pbb[b,t,h]) ----------------
__global__ __launch_bounds__(256) void score_kernel(
    const float* __restrict__ pa, const float* __restrict__ pb,
    const float* __restrict__ w2, const float* __restrict__ b2,
    float* __restrict__ out)
{
    extern __shared__ float sm[];
    float* paT = sm;                 // [512][17]
    float* pbT = sm + 512 * 17;
    float* w2s = pbT + 512 * 17;     // [512]

    const int tid = threadIdx.x;
    const int btt = blockIdx.x, bss = blockIdx.y, b = blockIdx.z;

    for (int idx = tid; idx < 16 * 512; idx += 256) {
        int row = idx >> 9, h = idx & 511;
        paT[h * 17 + row] = pa[(size_t)(b * SLEN + bss * 16 + row) * HID + h];
        pbT[h * 17 + row] = pb[(size_t)(b * SLEN + btt * 16 + row) * HID + h];
    }
    for (int idx = tid; idx < 512; idx += 256) w2s[idx] = w2[idx];
    __syncthreads();

    const int si = tid & 15, ti = tid >> 4;
    float acc = 0.0f;
#pragma unroll 8
    for (int h = 0; h < 512; h++) {
        float x = paT[h * 17 + si] + pbT[h * 17 + ti];
        acc = fmaf(w2s[h], tanh_fast(x), acc);
    }
    out[(size_t)(b * SLEN + bss * 16 + si) * SLEN + btt * 16 + ti] = acc + b2[0];
}

// ---------------- launch ----------------
extern "C" void kernel_launch(void* const* d_in, const int* in_sizes, int n_in,
                              void* d_out, int out_size)
{
    const int*   sent   = (const int*)d_in[0];
    const int*   pos    = (const int*)d_in[1];
    const int*   length = (const int*)d_in[2];
    const float* emb    = (const float*)d_in[3];
    const float* w_ih   = (const float*)d_in[4];
    const float* w_hh   = (const float*)d_in[5];
    const float* b_ih   = (const float*)d_in[6];
    const float* b_hh   = (const float*)d_in[7];
    const float* w1     = (const float*)d_in[8];
    const float* b1     = (const float*)d_in[9];
    const float* w2     = (const float*)d_in[10];
    const float* b2     = (const float*)d_in[11];
    float* out = (float*)d_out;

    const int SCORE_SMEM = 2 * 512 * 17 * 4 + 512 * 4;
    cudaFuncSetAttribute(score_kernel, cudaFuncAttributeMaxDynamicSharedMemorySize, SCORE_SMEM);

    float *xA, *xB, *prep, *pap, *pbp;
    cudaGetSymbolAddress((void**)&xA,   g_xA);
    cudaGetSymbolAddress((void**)&xB,   g_xB);
    cudaGetSymbolAddress((void**)&prep, g_pre);
    cudaGetSymbolAddress((void**)&pap,  g_pa);
    cudaGetSymbolAddress((void**)&pbp,  g_pb);

    zero_flags_kernel<<<NBLK_TOT * FLAG_PAD / 256, 256>>>();
    embed_kernel<<<1024, 256>>>(sent, pos, emb);

    for (int l = 0; l < 2; l++) {
        const float* Ain = l ? xB : xA;
        float* Xout      = l ? xA : xB;
        gemm_kernel<<<dim3(NPRE / 128, TOK / 128), 256>>>(
            Ain, w_ih + (size_t)l * NPRE * DINP, prep,
            NPRE, DINP, DINP, b_ih + l * NPRE, b_hh + l * NPRE);
        lstm_kernel<<<NBLK_TOT, 256>>>(
            prep, w_hh + (size_t)l * 2 * GHID * HID, length, Xout, l * SLEN);
    }

    gemm_kernel<<<dim3(HID / 128, TOK / 128), 256>>>(
        xA, w1,        pap, HID, DINP, 2048, nullptr, nullptr);
    gemm_kernel<<<dim3(HID / 128, TOK / 128), 256>>>(
        xA, w1 + 1024, pbp, HID, DINP, 2048, b1, nullptr);

    score_kernel<<<dim3(16, 16, 4), 256, SCORE_SMEM>>>(pap, pbp, w2, b2, out);
}

// round 11
// speedup vs baseline: 1.5304x; 1.0043x over previous
#include <cuda_runtime.h>
#include <math.h>
#include <stdint.h>

#define TOK   1024   // B*S
#define SLEN  256
#define BATCH 4
#define HID   512
#define DINP  1024
#define GHID  2048
#define NPRE  4096   // 2 dirs * 4H

#define NBLK     64      // blocks per direction in lstm kernel
#define NBLK_TOT 128
#define FLAG_PAD 32      // one 128B line per flag

typedef unsigned long long ull;

// ---------------- device scratch (static, no allocation) ----------------
__device__ float g_xA[TOK * DINP];
__device__ float g_xB[TOK * DINP];
__device__ float g_pre[TOK * NPRE];
__device__ float g_pa[TOK * HID];
__device__ float g_pb[TOK * HID];
__device__ float    g_h[2 * 2 * HID * 4];          // [buf][dir][k][batch]
__device__ unsigned g_flag[NBLK_TOT * FLAG_PAD];   // per-block step counters

// ---------------- helpers ----------------
__device__ __forceinline__ float tanh_fast(float x) {
    float y;
    asm("tanh.approx.f32 %0, %1;" : "=f"(y) : "f"(x));
    return y;
}
__device__ __forceinline__ float sig_fast(float x) {
    return 0.5f * tanh_fast(0.5f * x) + 0.5f;
}
__device__ __forceinline__ ull pk2(float x) {
    ull d; asm("mov.b64 %0, {%1, %1};" : "=l"(d) : "f"(x)); return d;
}
__device__ __forceinline__ void fma2(ull& acc, ull a, ull b) {
    asm("fma.rn.f32x2 %0, %1, %2, %0;" : "+l"(acc) : "l"(a), "l"(b));
}
__device__ __forceinline__ void add2(ull& acc, ull a) {
    asm("add.rn.f32x2 %0, %0, %1;" : "+l"(acc) : "l"(a));
}
__device__ __forceinline__ float lo2(ull v) { return __uint_as_float((unsigned)v); }
__device__ __forceinline__ float hi2(ull v) { return __uint_as_float((unsigned)(v >> 32)); }
__device__ __forceinline__ unsigned ld_acq(const unsigned* p) {
    unsigned v;
    asm volatile("ld.acquire.gpu.global.b32 %0, [%1];" : "=r"(v) : "l"(p));
    return v;
}
__device__ __forceinline__ void st_rel(unsigned* p, unsigned v) {
    asm volatile("st.release.gpu.global.b32 [%0], %1;" :: "l"(p), "r"(v));
}
__device__ __forceinline__ void backoff() {
    asm volatile("nanosleep.u32 100;");
}

__global__ void zero_flags_kernel() {
    g_flag[blockIdx.x * 256 + threadIdx.x] = 0u;
}

// ---------------- embedding gather + concat ----------------
__global__ __launch_bounds__(256) void embed_kernel(
    const int* __restrict__ sent, const int* __restrict__ pos,
    const float* __restrict__ emb)
{
    int gid = blockIdx.x * 256 + threadIdx.x;
    int token = gid >> 8;
    int q = gid & 255;
    const float4* src;
    if (q < 128) src = (const float4*)(emb + (size_t)sent[token] * HID) + q;
    else         src = (const float4*)(emb + (size_t)pos[token]  * HID) + (q - 128);
    ((float4*)g_xA)[gid] = *src;
}

// ---------------- fp32x2 SIMT GEMM: C[M,N] = A[M,K] * B[N,K]^T + bias(n) ----------------
__global__ __launch_bounds__(256) void gemm_kernel(
    const float* __restrict__ A, const float* __restrict__ B,
    float* __restrict__ C, int N, int K, int ldb,
    const float* __restrict__ bias1, const float* __restrict__ bias2)
{
    __shared__ float As[16][128];
    __shared__ float Bs[16][128];
    const int tid = threadIdx.x;
    const int bm = blockIdx.y << 7, bn = blockIdx.x << 7;
    const int row = tid >> 1;
    const int kq  = (tid & 1) << 3;
    const int tx = tid & 15, ty = tid >> 4;
    const int n0 = tx << 2, m0 = ty << 2;

    const float* Ap = A + (size_t)(bm + row) * K + kq;
    const float* Bp = B + (size_t)(bn + row) * ldb + kq;

    ull acc[8][4];
#pragma unroll
    for (int i = 0; i < 8; i++)
#pragma unroll
        for (int j = 0; j < 4; j++) acc[i][j] = 0ull;

    float4 a0v = *(const float4*)(Ap);
    float4 a1v = *(const float4*)(Ap + 4);
    float4 b0v = *(const float4*)(Bp);
    float4 b1v = *(const float4*)(Bp + 4);

    for (int k0 = 0; k0 < K; k0 += 16) {
        As[kq + 0][row] = a0v.x; As[kq + 1][row] = a0v.y;
        As[kq + 2][row] = a0v.z; As[kq + 3][row] = a0v.w;
        As[kq + 4][row] = a1v.x; As[kq + 5][row] = a1v.y;
        As[kq + 6][row] = a1v.z; As[kq + 7][row] = a1v.w;
        Bs[kq + 0][row] = b0v.x; Bs[kq + 1][row] = b0v.y;
        Bs[kq + 2][row] = b0v.z; Bs[kq + 3][row] = b0v.w;
        Bs[kq + 4][row] = b1v.x; Bs[kq + 5][row] = b1v.y;
        Bs[kq + 6][row] = b1v.z; Bs[kq + 7][row] = b1v.w;
        __syncthreads();

        if (k0 + 16 < K) {
            a0v = *(const float4*)(Ap + k0 + 16);
            a1v = *(const float4*)(Ap + k0 + 20);
            b0v = *(const float4*)(Bp + k0 + 16);
            b1v = *(const float4*)(Bp + k0 + 20);
        }

#pragma unroll
        for (int k = 0; k < 16; k++) {
            float4 am0 = *(const float4*)&As[k][m0];
            float4 am1 = *(const float4*)&As[k][m0 + 64];
            ulonglong2 bb0 = *(const ulonglong2*)&Bs[k][n0];
            ulonglong2 bb1 = *(const ulonglong2*)&Bs[k][n0 + 64];
            ull ad[8];
            ad[0] = pk2(am0.x); ad[1] = pk2(am0.y); ad[2] = pk2(am0.z); ad[3] = pk2(am0.w);
            ad[4] = pk2(am1.x); ad[5] = pk2(am1.y); ad[6] = pk2(am1.z); ad[7] = pk2(am1.w);
#pragma unroll
            for (int i = 0; i < 8; i++) {
                fma2(acc[i][0], ad[i], bb0.x);
                fma2(acc[i][1], ad[i], bb0.y);
                fma2(acc[i][2], ad[i], bb1.x);
                fma2(acc[i][3], ad[i], bb1.y);
            }
        }
        __syncthreads();
    }

    float bz[8];
#pragma unroll
    for (int jj = 0; jj < 8; jj++) {
        int n = bn + n0 + ((jj < 4) ? jj : 60 + jj);
        float bb = 0.0f;
        if (bias1) bb += bias1[n];
        if (bias2) bb += bias2[n];
        bz[jj] = bb;
    }
#pragma unroll
    for (int i = 0; i < 8; i++) {
        int m = bm + m0 + ((i < 4) ? i : 60 + i);
        float* Cr = C + (size_t)m * N + bn + n0;
        Cr[0]  = lo2(acc[i][0]) + bz[0];
        Cr[1]  = hi2(acc[i][0]) + bz[1];
        Cr[2]  = lo2(acc[i][1]) + bz[2];
        Cr[3]  = hi2(acc[i][1]) + bz[3];
        Cr[64] = lo2(acc[i][2]) + bz[4];
        Cr[65] = hi2(acc[i][2]) + bz[5];
        Cr[66] = lo2(acc[i][3]) + bz[6];
        Cr[67] = hi2(acc[i][3]) + bz[7];
    }
}

// ---------------- persistent bidirectional LSTM scan (R10 base, spill-free weights) ----------------
// 128 blocks: [0,64) fwd, [64,128) bwd; each owns 8 hidden units (32 gate rows).
// Weights held as 64 scalar f32 registers (no spill); packed operand built with
// an inline mov.b64 (ALU pipe, dual-issues against fma pipe).
__global__ __launch_bounds__(256, 1) void lstm_kernel(
    const float* __restrict__ pre,     // [TOK][4096], bias folded
    const float* __restrict__ whh,     // [2][2048][512] this layer
    const int* __restrict__ length,
    float* __restrict__ xout,          // [TOK][1024]
    int base)                          // l*SLEN
{
    __shared__ float4 hbuf[512];       // h[k][4 batch]
    __shared__ ull    red2[512];       // matvec partials (packed batch pairs)
    __shared__ ull    gsum2[64];       // reduced gates  (packed batch pairs)

    const int tid = threadIdx.x;
    const int d   = blockIdx.x >> 6;
    const int blk = blockIdx.x & 63;
    const int u0  = blk * 8;
    const int r   = tid & 31;          // local gate-row (gate = r>>3, j = r&7)
    const int kc  = tid >> 5;          // k-chunk 0..7

    // register-resident scalar W_hh slice (64 f32 regs, no spill)
    float wreg[64];
    {
        const float* wp = whh + (size_t)d * GHID * HID
                        + (size_t)((r >> 3) * HID + u0 + (r & 7)) * HID + kc * 64;
#pragma unroll
        for (int kk = 0; kk < 64; kk++) wreg[kk] = wp[kk];
    }

    const bool is_w7 = (tid >= 224);
    const int lane = tid & 31;
    const int j7 = lane & 7, b7 = lane >> 3;
    float creg = 0.0f, hreg = 0.0f;
    const int len_b = is_w7 ? length[b7] : 0;

    unsigned* myflag = &g_flag[blockIdx.x * FLAG_PAD];
    const unsigned* dirflags = &g_flag[(d * NBLK) * FLAG_PAD];

    for (int s = 0; s < SLEN; s++) {
        const int t = d ? (SLEN - 1 - s) : s;

        // warp7: prefetch pre-activations for owned gates (independent of h)
        float pi = 0.f, pf = 0.f, pg = 0.f, po = 0.f;
        if (is_w7) {
            const float* pp = pre + (size_t)(b7 * SLEN + t) * NPRE + d * GHID + u0 + j7;
            pi = pp[0]; pf = pp[512]; pg = pp[1024]; po = pp[1536];
        }

        // all 256 threads: poll producer (tid>>2)'s flag, gather own 2 float4s
        if (s == 0) {
            hbuf[2 * tid]     = make_float4(0.f, 0.f, 0.f, 0.f);
            hbuf[2 * tid + 1] = make_float4(0.f, 0.f, 0.f, 0.f);
        } else {
            const unsigned want = (unsigned)(base + s);
            const unsigned* fl = dirflags + (tid >> 2) * FLAG_PAD;
            // first check free; then backoff-poll to avoid LTS queue storm
            if (ld_acq(fl) < want) {
                do { backoff(); } while (ld_acq(fl) < want);
            }
            const float4* src = ((const float4*)g_h) + ((s & 1) * 2 + d) * 512 + 2 * tid;
            hbuf[2 * tid]     = __ldcg(src);
            hbuf[2 * tid + 1] = __ldcg(src + 1);
        }
        __syncthreads();   // S1: hbuf ready

        // matvec: thread (r, kc), 64 k per thread, batch-packed f32x2
        ull a01 = 0ull, a23 = 0ull;
        const ulonglong2* hp = (const ulonglong2*)(hbuf + kc * 64);
#pragma unroll
        for (int kk = 0; kk < 64; kk++) {
            ulonglong2 hv = hp[kk];          // LDS.128 broadcast within warp
            ull wd = pk2(wreg[kk]);          // ALU mov, dual-issues vs fma pipe
            fma2(a01, wd, hv.x);
            fma2(a23, wd, hv.y);
        }
        red2[tid] = a01;
        red2[256 + tid] = a23;
        __syncthreads();   // S2

        // packed 8-way reduction: 64 threads
        if (tid < 64) {
            const int rr = tid & 31, half = tid >> 5;
            const ull* rp = red2 + half * 256 + rr;
            ull sum = rp[0];
#pragma unroll
            for (int q = 1; q < 8; q++) add2(sum, rp[q * 32]);
            gsum2[half * 32 + rr] = sum;
        }
        __syncthreads();   // S3

        // warp7: activation + publish (runs while other warps start next poll)
        if (is_w7) {
            const float* gs = (const float*)gsum2;
            const int bb = (b7 >> 1) * 64 + (b7 & 1);
            float gi = pi + gs[bb + (0 * 8 + j7) * 2];
            float gf = pf + gs[bb + (1 * 8 + j7) * 2];
            float gg = pg + gs[bb + (2 * 8 + j7) * 2];
            float go = po + gs[bb + (3 * 8 + j7) * 2];
            float cn = sig_fast(gf) * creg + sig_fast(gi) * tanh_fast(gg);
            float hn = sig_fast(go) * tanh_fast(cn);
            bool m = (t < len_b);
            if (m) { creg = cn; hreg = hn; }
            // publish h (buffer (s+1)&1): 32 consecutive floats = one 128B line
            __stcg(&((float*)g_h)[((((s + 1) & 1) * 2 + d) * 512 + u0 + j7) * 4 + b7], hreg);
            __syncwarp();                     // warp-scope memory order: h-line HB release
            if (lane == 0) st_rel(myflag, (unsigned)(base + s + 1));
            // xout after release: off the critical path
            xout[(size_t)(b7 * SLEN + t) * DINP + d * HID + u0 + j7] = m ? hn : 0.0f;
        }
    }
}

// ---------------- score: out[b,s,t] = b2 + sum_h w2[h]*tanh(pa[b,s,h]+pbb[b,t,h]) ----------------
__global__ __launch_bounds__(256) void score_kernel(
    const float* __restrict__ pa, const float* __restrict__ pb,
    const float* __restrict__ w2, const float* __restrict__ b2,
    float* __restrict__ out)
{
    extern __shared__ float sm[];
    float* paT = sm;                 // [512][17]
    float* pbT = sm + 512 * 17;
    float* w2s = pbT + 512 * 17;     // [512]

    const int tid = threadIdx.x;
    const int btt = blockIdx.x, bss = blockIdx.y, b = blockIdx.z;

    for (int idx = tid; idx < 16 * 512; idx += 256) {
        int row = idx >> 9, h = idx & 511;
        paT[h * 17 + row] = pa[(size_t)(b * SLEN + bss * 16 + row) * HID + h];
        pbT[h * 17 + row] = pb[(size_t)(b * SLEN + btt * 16 + row) * HID + h];
    }
    for (int idx = tid; idx < 512; idx += 256) w2s[idx] = w2[idx];
    __syncthreads();

    const int si = tid & 15, ti = tid >> 4;
    float acc = 0.0f;
#pragma unroll 8
    for (int h = 0; h < 512; h++) {
        float x = paT[h * 17 + si] + pbT[h * 17 + ti];
        acc = fmaf(w2s[h], tanh_fast(x), acc);
    }
    out[(size_t)(b * SLEN + bss * 16 + si) * SLEN + btt * 16 + ti] = acc + b2[0];
}

// ---------------- launch ----------------
extern "C" void kernel_launch(void* const* d_in, const int* in_sizes, int n_in,
                              void* d_out, int out_size)
{
    const int*   sent   = (const int*)d_in[0];
    const int*   pos    = (const int*)d_in[1];
    const int*   length = (const int*)d_in[2];
    const float* emb    = (const float*)d_in[3];
    const float* w_ih   = (const float*)d_in[4];
    const float* w_hh   = (const float*)d_in[5];
    const float* b_ih   = (const float*)d_in[6];
    const float* b_hh   = (const float*)d_in[7];
    const float* w1     = (const float*)d_in[8];
    const float* b1     = (const float*)d_in[9];
    const float* w2     = (const float*)d_in[10];
    const float* b2     = (const float*)d_in[11];
    float* out = (float*)d_out;

    const int SCORE_SMEM = 2 * 512 * 17 * 4 + 512 * 4;
    cudaFuncSetAttribute(score_kernel, cudaFuncAttributeMaxDynamicSharedMemorySize, SCORE_SMEM);

    float *xA, *xB, *prep, *pap, *pbp;
    cudaGetSymbolAddress((void**)&xA,   g_xA);
    cudaGetSymbolAddress((void**)&xB,   g_xB);
    cudaGetSymbolAddress((void**)&prep, g_pre);
    cudaGetSymbolAddress((void**)&pap,  g_pa);
    cudaGetSymbolAddress((void**)&pbp,  g_pb);

    zero_flags_kernel<<<NBLK_TOT * FLAG_PAD / 256, 256>>>();
    embed_kernel<<<1024, 256>>>(sent, pos, emb);

    for (int l = 0; l < 2; l++) {
        const float* Ain = l ? xB : xA;
        float* Xout      = l ? xA : xB;
        gemm_kernel<<<dim3(NPRE / 128, TOK / 128), 256>>>(
            Ain, w_ih + (size_t)l * NPRE * DINP, prep,
            NPRE, DINP, DINP, b_ih + l * NPRE, b_hh + l * NPRE);
        lstm_kernel<<<NBLK_TOT, 256>>>(
            prep, w_hh + (size_t)l * 2 * GHID * HID, length, Xout, l * SLEN);
    }

    gemm_kernel<<<dim3(HID / 128, TOK / 128), 256>>>(
        xA, w1,        pap, HID, DINP, 2048, nullptr, nullptr);
    gemm_kernel<<<dim3(HID / 128, TOK / 128), 256>>>(
        xA, w1 + 1024, pbp, HID, DINP, 2048, b1, nullptr);

    score_kernel<<<dim3(16, 16, 4), 256, SCORE_SMEM>>>(pap, pbp, w2, b2, out);
}